// round 1
// baseline (speedup 1.0000x reference)
#include <cuda_runtime.h>
#include <math.h>

#define BB 8
#define CC 128
#define LL 4096
#define DIN 256
#define NST 16
#define NCH 64
#define CHL 64

// ------------------------- scratch (static, no allocation) -------------------------
__device__ float g_xhraw[BB*LL*DIN];
__device__ float g_xh   [BB*LL*DIN];
__device__ float g_z    [BB*LL*DIN];
__device__ float g_dt   [BB*LL*DIN];
__device__ float g_Bm   [BB*LL*NST];
__device__ float g_Cm   [BB*LL*NST];
__device__ float g_y    [BB*LL*DIN];
__device__ float g_mo   [BB*CC*LL];
__device__ float g_hloc [BB*DIN*NCH*NST];
__device__ float g_dts  [BB*DIN*NCH];
__device__ float g_hst  [BB*DIN*NCH*NST];
__device__ float g_stat [BB*4*2];

__device__ __forceinline__ float siluf(float v){ return v / (1.f + __expf(-v)); }

// ------------------------- K1: in-projection GEMM -------------------------
// xz[b,l,j] = sum_c x_hsi[b,c,l] * W_in[c,j]   (j<256 -> xhraw, j>=256 -> z)
__global__ __launch_bounds__(256) void k_gemm_in(const float* __restrict__ x,
                                                 const float* __restrict__ Win){
  __shared__ float As[64][64];  // [k][l]
  __shared__ float Ws[64][64];  // [k][j]
  int b  = blockIdx.z;
  int l0 = blockIdx.y << 6;
  int j0 = blockIdx.x << 6;
  int tid = threadIdx.x;
  int ly = tid >> 4, jy = tid & 15;
  float acc[4][4];
  #pragma unroll
  for (int i=0;i<4;i++)
    #pragma unroll
    for (int j=0;j<4;j++) acc[i][j]=0.f;

  for (int kk = 0; kk < 128; kk += 64){
    #pragma unroll
    for (int i = tid; i < 1024; i += 256){
      int k = i >> 4, lq = (i & 15) << 2;
      *(float4*)&As[k][lq] = *(const float4*)&x[((size_t)(b*CC + kk + k)*LL) + l0 + lq];
    }
    #pragma unroll
    for (int i = tid; i < 1024; i += 256){
      int k = i >> 4, jq = (i & 15) << 2;
      *(float4*)&Ws[k][jq] = *(const float4*)&Win[(size_t)(kk + k)*512 + j0 + jq];
    }
    __syncthreads();
    #pragma unroll
    for (int k = 0; k < 64; k++){
      float4 av = *(float4*)&As[k][ly<<2];
      float4 wv = *(float4*)&Ws[k][jy<<2];
      float aa[4] = {av.x,av.y,av.z,av.w};
      float ww[4] = {wv.x,wv.y,wv.z,wv.w};
      #pragma unroll
      for (int i=0;i<4;i++)
        #pragma unroll
        for (int j=0;j<4;j++) acc[i][j] = fmaf(aa[i], ww[j], acc[i][j]);
    }
    __syncthreads();
  }
  int jg = j0 + (jy<<2);
  float* dst; int jj;
  if (jg < DIN){ dst = g_xhraw; jj = jg; } else { dst = g_z; jj = jg - DIN; }
  #pragma unroll
  for (int i=0;i<4;i++){
    int l = l0 + (ly<<2) + i;
    *(float4*)&dst[(size_t)(b*LL + l)*DIN + jj] =
        make_float4(acc[i][0],acc[i][1],acc[i][2],acc[i][3]);
  }
}

// ------------------------- K2: causal conv k=2 + SiLU -------------------------
__global__ __launch_bounds__(256) void k_conv(const float* __restrict__ cw,
                                              const float* __restrict__ cb){
  int i4 = blockIdx.x*256 + threadIdx.x;       // float4 index, total 2,097,152
  int d4  = i4 & 63;                           // DIN/4
  int row = i4 >> 6;                           // b*L + l
  int l   = row & (LL-1);
  float4 cur = ((const float4*)g_xhraw)[i4];
  float4 prev = (l==0) ? make_float4(0.f,0.f,0.f,0.f) : ((const float4*)g_xhraw)[i4 - 64];
  int d0 = d4 << 2;
  float c_[4] = {cur.x,cur.y,cur.z,cur.w};
  float p_[4] = {prev.x,prev.y,prev.z,prev.w};
  float r[4];
  #pragma unroll
  for (int j=0;j<4;j++){
    float w0 = __ldg(&cw[(d0+j)*2]);
    float w1 = __ldg(&cw[(d0+j)*2+1]);
    float v = fmaf(w0, p_[j], fmaf(w1, c_[j], __ldg(&cb[d0+j])));
    r[j] = siluf(v);
  }
  ((float4*)g_xh)[i4] = make_float4(r[0],r[1],r[2],r[3]);
}

// ------------------------- K3: x_dbl projection + dt -------------------------
__global__ __launch_bounds__(256) void k_xdbl(const float* __restrict__ Wx,
                                              const float* __restrict__ Wdt,
                                              const float* __restrict__ bdt){
  __shared__ float sx[32][260];    // padded to avoid 4-way bank conflict
  __shared__ float sdl[32][8];
  __shared__ float swd[2048];
  int b  = blockIdx.y;
  int l0 = blockIdx.x << 5;
  int tid = threadIdx.x;
  for (int i = tid; i < 2048; i += 256){       // 32*256/4 float4 loads
    int pos = i << 2;
    int l = pos >> 8, d = pos & 255;
    *(float4*)&sx[l][d] = *(const float4*)&g_xh[(size_t)(b*LL + l0 + l)*DIN + d];
  }
  for (int i = tid; i < 512; i += 256)
    *(float4*)&swd[i<<2] = *(const float4*)&Wdt[i<<2];
  __syncthreads();
  {
    int l  = tid >> 3;
    int kg = (tid & 7) * 5;
    float acc[5] = {0,0,0,0,0};
    for (int d = 0; d < DIN; d++){
      float xv = sx[l][d];
      #pragma unroll
      for (int i=0;i<5;i++) acc[i] = fmaf(xv, __ldg(&Wx[d*40 + kg + i]), acc[i]);
    }
    size_t lg = (size_t)(b*LL + l0 + l);
    #pragma unroll
    for (int i=0;i<5;i++){
      int k = kg + i;
      float v = acc[i];
      if      (k < 8)  sdl[l][k]            = v;
      else if (k < 24) g_Bm[lg*NST + (k-8)]  = v;
      else             g_Cm[lg*NST + (k-24)] = v;
    }
  }
  __syncthreads();
  {
    int d = tid;
    float bv = __ldg(&bdt[d]);
    for (int l = 0; l < 32; l++){
      float s = bv;
      #pragma unroll
      for (int r = 0; r < 8; r++) s = fmaf(sdl[l][r], swd[r*DIN + d], s);
      float dt = (s > 20.f) ? s : log1pf(__expf(s));   // softplus
      g_dt[(size_t)(b*LL + l0 + l)*DIN + d] = dt;
    }
  }
}

// ------------------------- K4a: per-chunk local scan -------------------------
__global__ __launch_bounds__(256) void k_scan_local(const float* __restrict__ A_log){
  __shared__ __align__(16) float sB[CHL][NST];
  int b = blockIdx.y, ch = blockIdx.x;
  int d = threadIdx.x;
  int l0 = ch * CHL;
  for (int i = threadIdx.x; i < CHL*NST/4; i += 256)
    ((float4*)sB)[i] = *(const float4*)&g_Bm[(size_t)(b*LL + l0)*NST + (i<<2)];
  __syncthreads();
  float a[NST];
  #pragma unroll
  for (int n=0;n<NST;n++) a[n] = -__expf(__ldg(&A_log[d*NST+n]));
  float h[NST];
  #pragma unroll
  for (int n=0;n<NST;n++) h[n]=0.f;
  float dtsum = 0.f;
  const float* dtp = &g_dt[(size_t)(b*LL + l0)*DIN + d];
  const float* xp  = &g_xh[(size_t)(b*LL + l0)*DIN + d];
  for (int t = 0; t < CHL; t++){
    float dtv = dtp[(size_t)t*DIN];
    float xv  = xp [(size_t)t*DIN];
    dtsum += dtv;
    float dx = dtv * xv;
    #pragma unroll
    for (int n=0;n<NST;n++)
      h[n] = fmaf(__expf(dtv*a[n]), h[n], dx * sB[t][n]);
  }
  size_t base = ((size_t)(b*DIN + d)*NCH + ch)*NST;
  #pragma unroll
  for (int n=0;n<NST;n+=4)
    *(float4*)&g_hloc[base+n] = make_float4(h[n],h[n+1],h[n+2],h[n+3]);
  g_dts[(size_t)(b*DIN + d)*NCH + ch] = dtsum;
}

// ------------------------- K4b: prefix over chunks -------------------------
__global__ __launch_bounds__(256) void k_scan_prefix(const float* __restrict__ A_log){
  int gt = blockIdx.x*256 + threadIdx.x;   // 8192 threads: (b, d, quad-of-states)
  int b = gt >> 10;
  int d = (gt >> 2) & 255;
  int q = gt & 3;
  float a[4];
  #pragma unroll
  for (int i=0;i<4;i++) a[i] = -__expf(__ldg(&A_log[d*NST + q*4 + i]));
  float c0=0.f,c1=0.f,c2=0.f,c3=0.f;
  size_t base = (size_t)(b*DIN + d)*NCH;
  for (int c = 0; c < NCH; c++){
    size_t off = (base + c)*NST + (q<<2);
    *(float4*)&g_hst[off] = make_float4(c0,c1,c2,c3);
    float ds = g_dts[base + c];
    float4 hl = *(const float4*)&g_hloc[off];
    c0 = fmaf(__expf(a[0]*ds), c0, hl.x);
    c1 = fmaf(__expf(a[1]*ds), c1, hl.y);
    c2 = fmaf(__expf(a[2]*ds), c2, hl.z);
    c3 = fmaf(__expf(a[3]*ds), c3, hl.w);
  }
}

// ------------------------- K4c: final scan + gate -------------------------
__global__ __launch_bounds__(256) void k_scan_final(const float* __restrict__ A_log,
                                                    const float* __restrict__ Dv){
  __shared__ __align__(16) float sB[CHL][NST];
  __shared__ __align__(16) float sC[CHL][NST];
  int b = blockIdx.y, ch = blockIdx.x;
  int d = threadIdx.x;
  int l0 = ch * CHL;
  {
    int i = threadIdx.x;   // exactly 256 float4 each
    ((float4*)sB)[i] = *(const float4*)&g_Bm[(size_t)(b*LL + l0)*NST + (i<<2)];
    ((float4*)sC)[i] = *(const float4*)&g_Cm[(size_t)(b*LL + l0)*NST + (i<<2)];
  }
  __syncthreads();
  float a[NST], h[NST];
  #pragma unroll
  for (int n=0;n<NST;n++) a[n] = -__expf(__ldg(&A_log[d*NST+n]));
  size_t hb = ((size_t)(b*DIN + d)*NCH + ch)*NST;
  #pragma unroll
  for (int n=0;n<NST;n+=4){
    float4 v = *(const float4*)&g_hst[hb+n];
    h[n]=v.x; h[n+1]=v.y; h[n+2]=v.z; h[n+3]=v.w;
  }
  float Dd = __ldg(&Dv[d]);
  const float* dtp = &g_dt[(size_t)(b*LL + l0)*DIN + d];
  const float* xp  = &g_xh[(size_t)(b*LL + l0)*DIN + d];
  const float* zp  = &g_z [(size_t)(b*LL + l0)*DIN + d];
  float* yp        = &g_y [(size_t)(b*LL + l0)*DIN + d];
  for (int t = 0; t < CHL; t++){
    float dtv = dtp[(size_t)t*DIN];
    float xv  = xp [(size_t)t*DIN];
    float dx = dtv*xv;
    float y = 0.f;
    #pragma unroll
    for (int n=0;n<NST;n++){
      h[n] = fmaf(__expf(dtv*a[n]), h[n], dx*sB[t][n]);
      y = fmaf(h[n], sC[t][n], y);
    }
    y = fmaf(xv, Dd, y);
    float zv = zp[(size_t)t*DIN];
    yp[(size_t)t*DIN] = y * siluf(zv);
  }
}

// ------------------------- K5: out-projection GEMM (writes (B,C,L)) -------------------------
__global__ __launch_bounds__(256) void k_gemm_out(const float* __restrict__ Wout){
  __shared__ float As[64][64];  // [l][k]
  __shared__ float Ws[64][64];  // [k][c]
  int b  = blockIdx.z;
  int l0 = blockIdx.y << 6;
  int c0 = blockIdx.x << 6;
  int tid = threadIdx.x;
  int ly = tid >> 4, cy = tid & 15;
  float acc[4][4];
  #pragma unroll
  for (int i=0;i<4;i++)
    #pragma unroll
    for (int j=0;j<4;j++) acc[i][j]=0.f;

  for (int kk = 0; kk < 256; kk += 64){
    #pragma unroll
    for (int i = tid; i < 1024; i += 256){
      int l = i >> 4, kq = (i & 15) << 2;
      *(float4*)&As[l][kq] = *(const float4*)&g_y[(size_t)(b*LL + l0 + l)*DIN + kk + kq];
    }
    #pragma unroll
    for (int i = tid; i < 1024; i += 256){
      int k = i >> 4, cq = (i & 15) << 2;
      *(float4*)&Ws[k][cq] = *(const float4*)&Wout[(size_t)(kk + k)*CC + c0 + cq];
    }
    __syncthreads();
    #pragma unroll
    for (int k = 0; k < 64; k++){
      float a0 = As[(ly<<2)  ][k];
      float a1 = As[(ly<<2)+1][k];
      float a2 = As[(ly<<2)+2][k];
      float a3 = As[(ly<<2)+3][k];
      float4 wv = *(float4*)&Ws[k][cy<<2];
      float ww[4] = {wv.x,wv.y,wv.z,wv.w};
      #pragma unroll
      for (int j=0;j<4;j++){
        acc[0][j] = fmaf(a0, ww[j], acc[0][j]);
        acc[1][j] = fmaf(a1, ww[j], acc[1][j]);
        acc[2][j] = fmaf(a2, ww[j], acc[2][j]);
        acc[3][j] = fmaf(a3, ww[j], acc[3][j]);
      }
    }
    __syncthreads();
  }
  #pragma unroll
  for (int j=0;j<4;j++){
    int c = c0 + (cy<<2) + j;
    *(float4*)&g_mo[(size_t)(b*CC + c)*LL + l0 + (ly<<2)] =
        make_float4(acc[0][j],acc[1][j],acc[2][j],acc[3][j]);
  }
}

// ------------------------- K6: group-norm stats -------------------------
__global__ __launch_bounds__(256) void k_gn_stats(){
  int b = blockIdx.y, g = blockIdx.x;
  const float4* p = (const float4*)&g_mo[((size_t)b*CC + g*32)*LL];
  float s = 0.f, ss = 0.f;
  for (int i = threadIdx.x; i < 32768; i += 256){
    float4 v = p[i];
    s  += v.x+v.y+v.z+v.w;
    ss += v.x*v.x + v.y*v.y + v.z*v.z + v.w*v.w;
  }
  __shared__ float rs[256], rss[256];
  rs[threadIdx.x]=s; rss[threadIdx.x]=ss; __syncthreads();
  for (int st=128; st>0; st>>=1){
    if (threadIdx.x < st){
      rs [threadIdx.x] += rs [threadIdx.x+st];
      rss[threadIdx.x] += rss[threadIdx.x+st];
    }
    __syncthreads();
  }
  if (threadIdx.x==0){
    float inv = 1.f/131072.f;
    float mean = rs[0]*inv;
    float var  = rss[0]*inv - mean*mean;
    g_stat[(b*4+g)*2]   = mean;
    g_stat[(b*4+g)*2+1] = rsqrtf(var + 1e-5f);
  }
}

// ------------------------- K7: GN apply + SiLU + residual -------------------------
__global__ __launch_bounds__(256) void k_final(const float* __restrict__ x_hsi,
                                               const float* __restrict__ gamma,
                                               const float* __restrict__ beta,
                                               float* __restrict__ out){
  int i4  = blockIdx.x*256 + threadIdx.x;   // 1,048,576 float4
  int idx = i4 << 2;
  int b = idx >> 19;           // / (128*4096)
  int c = (idx >> 12) & 127;
  int g = c >> 5;
  float mean = g_stat[(b*4+g)*2];
  float rstd = g_stat[(b*4+g)*2+1];
  float ga = __ldg(&gamma[c]);
  float be = __ldg(&beta[c]);
  float4 v  = *(const float4*)&g_mo[idx];
  float4 xo = *(const float4*)&x_hsi[idx];
  float vi[4] = {v.x,v.y,v.z,v.w};
  float xi[4] = {xo.x,xo.y,xo.z,xo.w};
  float ro[4];
  #pragma unroll
  for (int j=0;j<4;j++){
    float n = fmaf((vi[j]-mean)*rstd, ga, be);
    ro[j] = siluf(n) + xi[j];
  }
  *(float4*)&out[idx] = make_float4(ro[0],ro[1],ro[2],ro[3]);
}

// ------------------------- launch -------------------------
extern "C" void kernel_launch(void* const* d_in, const int* in_sizes, int n_in,
                              void* d_out, int out_size){
  const float* x_hsi  = (const float*)d_in[0];
  const float* W_in   = (const float*)d_in[1];
  const float* conv_w = (const float*)d_in[2];
  const float* conv_b = (const float*)d_in[3];
  const float* W_x    = (const float*)d_in[4];
  const float* W_dt   = (const float*)d_in[5];
  const float* b_dt   = (const float*)d_in[6];
  const float* A_log  = (const float*)d_in[7];
  const float* Dv     = (const float*)d_in[8];
  const float* W_out  = (const float*)d_in[9];
  const float* gamma  = (const float*)d_in[10];
  const float* beta   = (const float*)d_in[11];
  float* out = (float*)d_out;

  k_gemm_in   <<<dim3(8,64,8),  256>>>(x_hsi, W_in);
  k_conv      <<<8192,          256>>>(conv_w, conv_b);
  k_xdbl      <<<dim3(128,8),   256>>>(W_x, W_dt, b_dt);
  k_scan_local<<<dim3(NCH,BB),  256>>>(A_log);
  k_scan_prefix<<<32,           256>>>(A_log);
  k_scan_final<<<dim3(NCH,BB),  256>>>(A_log, Dv);
  k_gemm_out  <<<dim3(2,64,8),  256>>>(W_out);
  k_gn_stats  <<<dim3(4,8),     256>>>();
  k_final     <<<4096,          256>>>(x_hsi, gamma, beta, out);
}